// round 3
// baseline (speedup 1.0000x reference)
#include <cuda_runtime.h>
#include <math.h>

#define BATCH 2
#define LSEQ 2048
#define DMODEL 768
#define DINNER 1536
#define NSTATE 16
#define DTRANK 48
#define NROWS (BATCH*LSEQ)   /* 4096 */
#define DBC_W (DTRANK + 2*NSTATE)  /* 80 */

// ---- scratch (static device globals; no runtime allocation) ----
__device__ float g_xn[NROWS*DMODEL];        // layernorm out
__device__ float g_xr[(size_t)NROWS*2*DINNER]; // in_proj out (xin | res)
__device__ float g_xc[NROWS*DINNER];        // conv+silu out (u)
__device__ float g_dbc[NROWS*DBC_W];        // x_proj out (dt | B | C)
__device__ float g_delta[NROWS*DINNER];     // softplus(dt@W^T+b)
__device__ float g_y[NROWS*DINNER];         // scan out * silu(res)

// ---------------- LayerNorm ----------------
__global__ void ln_kernel(const float* __restrict__ x,
                          const float* __restrict__ w,
                          const float* __restrict__ b,
                          float* __restrict__ out) {
    __shared__ float red[256];
    int row = blockIdx.x;
    int t = threadIdx.x;
    const float* xp = x + (size_t)row * DMODEL;
    float s = 0.f;
    #pragma unroll
    for (int i = 0; i < 3; i++) s += xp[t + i*256];
    red[t] = s; __syncthreads();
    for (int o = 128; o > 0; o >>= 1) { if (t < o) red[t] += red[t+o]; __syncthreads(); }
    float mu = red[0] / DMODEL;
    __syncthreads();
    float v = 0.f;
    #pragma unroll
    for (int i = 0; i < 3; i++) { float d = xp[t + i*256] - mu; v += d*d; }
    red[t] = v; __syncthreads();
    for (int o = 128; o > 0; o >>= 1) { if (t < o) red[t] += red[t+o]; __syncthreads(); }
    float rstd = rsqrtf(red[0] / DMODEL + 1e-5f);
    float* op = out + (size_t)row * DMODEL;
    #pragma unroll
    for (int i = 0; i < 3; i++) {
        int c = t + i*256;
        op[c] = (xp[c] - mu) * rstd * w[c] + b[c];
    }
}

// ---------------- SGEMM (C = A * B^T), 128x128x8 tiles ----------------
// A: MxK row-major (lda), B: NxK row-major (ldb), C: MxN row-major (ldc)
// EPI==1: C = softplus(acc + bias[n])
__device__ __forceinline__ float softplus_f(float x) {
    return fmaxf(x, 0.f) + log1pf(expf(-fabsf(x)));
}

template<int EPI>
__global__ void sgemm_nt(const float* __restrict__ A, int lda,
                         const float* __restrict__ B, int ldb,
                         float* __restrict__ C, int ldc,
                         int N, int K,
                         const float* __restrict__ bias) {
    __shared__ float As[8][132];
    __shared__ float Bs[8][132];
    const int t = threadIdx.x;                 // 256
    const int block_m = blockIdx.y * 128;
    const int block_n = blockIdx.x * 128;
    const int lr = t >> 1;                     // 0..127
    const int lk = (t & 1) * 4;                // 0 or 4
    const int tm = (t >> 4) * 8;
    const int tn = (t & 15) * 8;

    float acc[8][8];
    #pragma unroll
    for (int i = 0; i < 8; i++)
        #pragma unroll
        for (int j = 0; j < 8; j++) acc[i][j] = 0.f;

    for (int k0 = 0; k0 < K; k0 += 8) {
        {
            int m = block_m + lr;
            float4 av = *reinterpret_cast<const float4*>(A + (size_t)m*lda + k0 + lk);
            As[lk+0][lr]=av.x; As[lk+1][lr]=av.y; As[lk+2][lr]=av.z; As[lk+3][lr]=av.w;
        }
        {
            int n = block_n + lr;
            float4 bv = make_float4(0.f,0.f,0.f,0.f);
            if (n < N) bv = *reinterpret_cast<const float4*>(B + (size_t)n*ldb + k0 + lk);
            Bs[lk+0][lr]=bv.x; Bs[lk+1][lr]=bv.y; Bs[lk+2][lr]=bv.z; Bs[lk+3][lr]=bv.w;
        }
        __syncthreads();
        #pragma unroll
        for (int kk = 0; kk < 8; kk++) {
            float4 a0 = *reinterpret_cast<const float4*>(&As[kk][tm]);
            float4 a1 = *reinterpret_cast<const float4*>(&As[kk][tm+4]);
            float4 b0 = *reinterpret_cast<const float4*>(&Bs[kk][tn]);
            float4 b1 = *reinterpret_cast<const float4*>(&Bs[kk][tn+4]);
            float ra[8] = {a0.x,a0.y,a0.z,a0.w,a1.x,a1.y,a1.z,a1.w};
            float rb[8] = {b0.x,b0.y,b0.z,b0.w,b1.x,b1.y,b1.z,b1.w};
            #pragma unroll
            for (int i = 0; i < 8; i++)
                #pragma unroll
                for (int j = 0; j < 8; j++)
                    acc[i][j] = fmaf(ra[i], rb[j], acc[i][j]);
        }
        __syncthreads();
    }

    if (EPI == 0 && block_n + 128 <= N) {
        #pragma unroll
        for (int i = 0; i < 8; i++) {
            float* cp = C + (size_t)(block_m + tm + i)*ldc + block_n + tn;
            float4 v0 = make_float4(acc[i][0],acc[i][1],acc[i][2],acc[i][3]);
            float4 v1 = make_float4(acc[i][4],acc[i][5],acc[i][6],acc[i][7]);
            *reinterpret_cast<float4*>(cp) = v0;
            *reinterpret_cast<float4*>(cp+4) = v1;
        }
    } else {
        #pragma unroll
        for (int i = 0; i < 8; i++) {
            float* cp = C + (size_t)(block_m + tm + i)*ldc;
            #pragma unroll
            for (int j = 0; j < 8; j++) {
                int n = block_n + tn + j;
                if (n < N) {
                    float v = acc[i][j];
                    if (EPI == 1) v = softplus_f(v + bias[n]);
                    cp[n] = v;
                }
            }
        }
    }
}

// ---------------- depthwise causal conv (width 4) + SiLU ----------------
__global__ void conv_silu_kernel(const float* __restrict__ xr,
                                 const float* __restrict__ w,
                                 const float* __restrict__ cb,
                                 float* __restrict__ out) {
    int idx = blockIdx.x * blockDim.x + threadIdx.x; // over NROWS*DINNER
    int d = idx % DINNER;
    int row = idx / DINNER;
    int l = row % LSEQ;
    const float* xp = xr + (size_t)row * (2*DINNER) + d;
    float acc = cb[d];
    const float* wp = w + d*4;
    #pragma unroll
    for (int j = 0; j < 4; j++) {
        int ll = l - 3 + j;
        if (ll >= 0) acc = fmaf(wp[j], xp[(long)(ll - l) * (2*DINNER)], acc);
    }
    out[idx] = acc / (1.f + __expf(-acc));
}

// ---------------- selective scan (+ D skip + gate) ----------------
// one thread per (b,d); 16 states in registers
__global__ void scan_kernel(const float* __restrict__ xc,
                            const float* __restrict__ delta,
                            const float* __restrict__ dbc,
                            const float* __restrict__ xr,
                            const float* __restrict__ A_log,
                            const float* __restrict__ Dp,
                            float* __restrict__ y) {
    int bidx = blockIdx.x;              // 24 blocks: 12 per batch
    int b = bidx / (DINNER/128);
    int d = (bidx % (DINNER/128)) * 128 + threadIdx.x;

    float a[16], h[16];
    #pragma unroll
    for (int n = 0; n < 16; n++) { a[n] = -expf(A_log[d*16 + n]); h[n] = 0.f; }
    float Dv = Dp[d];

    const float* dptr  = delta + (size_t)b*LSEQ*DINNER + d;
    const float* uptr  = xc    + (size_t)b*LSEQ*DINNER + d;
    const float* rptr  = xr    + (size_t)b*LSEQ*(2*DINNER) + DINNER + d;
    const float* bcptr = dbc   + (size_t)b*LSEQ*DBC_W + DTRANK;
    float* yptr        = y     + (size_t)b*LSEQ*DINNER + d;

    for (int l = 0; l < LSEQ; l++) {
        float dl = dptr[0];
        float u  = uptr[0];
        const float4* p = reinterpret_cast<const float4*>(bcptr);
        float4 t0=p[0], t1=p[1], t2=p[2], t3=p[3];   // B
        float4 c0=p[4], c1=p[5], c2=p[6], c3=p[7];   // C
        float bb[16] = {t0.x,t0.y,t0.z,t0.w, t1.x,t1.y,t1.z,t1.w,
                        t2.x,t2.y,t2.z,t2.w, t3.x,t3.y,t3.z,t3.w};
        float cc[16] = {c0.x,c0.y,c0.z,c0.w, c1.x,c1.y,c1.z,c1.w,
                        c2.x,c2.y,c2.z,c2.w, c3.x,c3.y,c3.z,c3.w};
        float du = dl * u;
        float accv = 0.f;
        #pragma unroll
        for (int n = 0; n < 16; n++) {
            float e = __expf(dl * a[n]);
            h[n] = fmaf(e, h[n], du * bb[n]);
            accv = fmaf(h[n], cc[n], accv);
        }
        float r = rptr[0];
        float g = r / (1.f + __expf(-r));
        yptr[0] = (accv + u * Dv) * g;

        dptr += DINNER; uptr += DINNER; rptr += 2*DINNER; bcptr += DBC_W; yptr += DINNER;
    }
}

// ---------------- launch ----------------
extern "C" void kernel_launch(void* const* d_in, const int* in_sizes, int n_in,
                              void* d_out, int out_size) {
    const float* x         = (const float*)d_in[0];
    const float* ln_w      = (const float*)d_in[1];
    const float* ln_b      = (const float*)d_in[2];
    const float* in_proj_w = (const float*)d_in[3];
    const float* conv_w    = (const float*)d_in[4];
    const float* conv_b    = (const float*)d_in[5];
    const float* x_proj_w  = (const float*)d_in[6];
    const float* dt_proj_w = (const float*)d_in[7];
    const float* dt_proj_b = (const float*)d_in[8];
    const float* A_log     = (const float*)d_in[9];
    const float* D_param   = (const float*)d_in[10];
    const float* out_proj_w= (const float*)d_in[11];
    float* out = (float*)d_out;

    float *p_xn, *p_xr, *p_xc, *p_dbc, *p_delta, *p_y;
    cudaGetSymbolAddress((void**)&p_xn, g_xn);
    cudaGetSymbolAddress((void**)&p_xr, g_xr);
    cudaGetSymbolAddress((void**)&p_xc, g_xc);
    cudaGetSymbolAddress((void**)&p_dbc, g_dbc);
    cudaGetSymbolAddress((void**)&p_delta, g_delta);
    cudaGetSymbolAddress((void**)&p_y, g_y);

    // 1. LayerNorm
    ln_kernel<<<NROWS, 256>>>(x, ln_w, ln_b, p_xn);

    // 2. in_proj: (4096x768) @ (3072x768)^T -> (4096x3072)
    sgemm_nt<0><<<dim3(2*DINNER/128, NROWS/128), 256>>>(
        p_xn, DMODEL, in_proj_w, DMODEL, p_xr, 2*DINNER, 2*DINNER, DMODEL, nullptr);

    // 3. conv + silu -> u
    conv_silu_kernel<<<(NROWS*DINNER)/256, 256>>>(p_xr, conv_w, conv_b, p_xc);

    // 4. x_proj: (4096x1536) @ (80x1536)^T -> (4096x80)
    sgemm_nt<0><<<dim3(1, NROWS/128), 256>>>(
        p_xc, DINNER, x_proj_w, DINNER, p_dbc, DBC_W, DBC_W, DINNER, nullptr);

    // 5. dt_proj + bias + softplus: (4096x48) @ (1536x48)^T -> (4096x1536)
    sgemm_nt<1><<<dim3(DINNER/128, NROWS/128), 256>>>(
        p_dbc, DBC_W, dt_proj_w, DTRANK, p_delta, DINNER, DINNER, DTRANK, dt_proj_b);

    // 6. selective scan + D skip + gate
    scan_kernel<<<BATCH*(DINNER/128), 128>>>(
        p_xc, p_delta, p_dbc, p_xr, A_log, D_param, p_y);

    // 7. out_proj: (4096x1536) @ (768x1536)^T -> (4096x768)
    sgemm_nt<0><<<dim3(DMODEL/128, NROWS/128), 256>>>(
        p_y, DINNER, out_proj_w, DINNER, out, DMODEL, DMODEL, DINNER, nullptr);
}

// round 5
// speedup vs baseline: 1.3220x; 1.3220x over previous
#include <cuda_runtime.h>
#include <cuda_bf16.h>
#include <stdint.h>
#include <math.h>

#define BATCH 2
#define LSEQ 2048
#define DMODEL 768
#define DINNER 1536
#define NSTATE 16
#define DTRANK 48
#define NROWS (BATCH*LSEQ)   /* 4096 */
#define DBC_W (DTRANK + 2*NSTATE)  /* 80 */

#define APAD 40   /* bf16 elems per smem row (80B = 20-bank rotation, conflict-free) */

// ---- scratch (static device globals; no runtime allocation) ----
__device__ float g_xn[NROWS*DMODEL];           // layernorm out
__device__ float g_xr[(size_t)NROWS*2*DINNER]; // in_proj out (xin | res)
__device__ float g_xc[NROWS*DINNER];           // conv+silu out (u)
__device__ float g_dbc[NROWS*DBC_W];           // x_proj out (dt | B | C)
__device__ float g_delta[NROWS*DINNER];        // softplus(dt@W^T+b)
__device__ float g_y[NROWS*DINNER];            // scan out * silu(res)

// ---------------- LayerNorm ----------------
__global__ void ln_kernel(const float* __restrict__ x,
                          const float* __restrict__ w,
                          const float* __restrict__ b,
                          float* __restrict__ out) {
    __shared__ float red[256];
    int row = blockIdx.x;
    int t = threadIdx.x;
    const float* xp = x + (size_t)row * DMODEL;
    float s = 0.f;
    #pragma unroll
    for (int i = 0; i < 3; i++) s += xp[t + i*256];
    red[t] = s; __syncthreads();
    for (int o = 128; o > 0; o >>= 1) { if (t < o) red[t] += red[t+o]; __syncthreads(); }
    float mu = red[0] / DMODEL;
    __syncthreads();
    float v = 0.f;
    #pragma unroll
    for (int i = 0; i < 3; i++) { float d = xp[t + i*256] - mu; v += d*d; }
    red[t] = v; __syncthreads();
    for (int o = 128; o > 0; o >>= 1) { if (t < o) red[t] += red[t+o]; __syncthreads(); }
    float rstd = rsqrtf(red[0] / DMODEL + 1e-5f);
    float* op = out + (size_t)row * DMODEL;
    #pragma unroll
    for (int i = 0; i < 3; i++) {
        int c = t + i*256;
        op[c] = (xp[c] - mu) * rstd * w[c] + b[c];
    }
}

__device__ __forceinline__ float softplus_f(float x) {
    return fmaxf(x, 0.f) + log1pf(expf(-fabsf(x)));
}

// ---------------- bf16-split tensor-core GEMM: C = A * B^T ----------------
// A: MxK row-major (lda), B: NxK row-major (ldb), C: MxN row-major (ldc)
// fp32 inputs split into bf16 hi+lo during smem staging; 3 HMMA per logical mma.
// Block tile 128x128, K-stage 32, 8 warps as 2(m)x4(n), warp tile 64x32.
// M must be a multiple of 128 and covered exactly by grid.y. N guarded (mult of 8).
// EPI==1: C = softplus(acc + bias[n])

#define MMA_BF16(C, A0,A1,A2,A3, B0,B1)                                   \
    asm volatile("mma.sync.aligned.m16n8k16.row.col.f32.bf16.bf16.f32 "   \
        "{%0,%1,%2,%3}, {%4,%5,%6,%7}, {%8,%9}, {%0,%1,%2,%3};"           \
        : "+f"(C[0]), "+f"(C[1]), "+f"(C[2]), "+f"(C[3])                  \
        : "r"(A0), "r"(A1), "r"(A2), "r"(A3), "r"(B0), "r"(B1))

__device__ __forceinline__ float4 ld4g(const float* p, bool pred) {
    if (pred) return *reinterpret_cast<const float4*>(p);
    return make_float4(0.f, 0.f, 0.f, 0.f);
}

__device__ __forceinline__ void cvt_store(float4 v,
                                          __nv_bfloat16* hi,
                                          __nv_bfloat16* lo) {
    __nv_bfloat16 h0 = __float2bfloat16(v.x), h1 = __float2bfloat16(v.y);
    __nv_bfloat16 h2 = __float2bfloat16(v.z), h3 = __float2bfloat16(v.w);
    __nv_bfloat16 l0 = __float2bfloat16(v.x - __bfloat162float(h0));
    __nv_bfloat16 l1 = __float2bfloat16(v.y - __bfloat162float(h1));
    __nv_bfloat16 l2 = __float2bfloat16(v.z - __bfloat162float(h2));
    __nv_bfloat16 l3 = __float2bfloat16(v.w - __bfloat162float(h3));
    __nv_bfloat162 p;
    p.x = h0; p.y = h1; *reinterpret_cast<__nv_bfloat162*>(hi)     = p;
    p.x = h2; p.y = h3; *reinterpret_cast<__nv_bfloat162*>(hi + 2) = p;
    p.x = l0; p.y = l1; *reinterpret_cast<__nv_bfloat162*>(lo)     = p;
    p.x = l2; p.y = l3; *reinterpret_cast<__nv_bfloat162*>(lo + 2) = p;
}

template<int EPI>
__global__ __launch_bounds__(256, 1)
void mma_nt(const float* __restrict__ A, int lda,
            const float* __restrict__ B, int ldb,
            float* __restrict__ C, int ldc,
            int N, int K,
            const float* __restrict__ bias) {
    __shared__ __nv_bfloat16 Ahi[128*APAD];
    __shared__ __nv_bfloat16 Alo[128*APAD];
    __shared__ __nv_bfloat16 Bhi[128*APAD];
    __shared__ __nv_bfloat16 Blo[128*APAD];

    const int t = threadIdx.x;
    const int bm = blockIdx.y * 128;
    const int bn = blockIdx.x * 128;
    const int warp = t >> 5, lane = t & 31;
    const int wm = (warp >> 2) * 64;   // warp m-base within block
    const int wn = (warp & 3) * 32;    // warp n-base within block
    const int g = lane >> 2;           // group 0..7
    const int q = (lane & 3) * 2;      // k-pair offset 0,2,4,6

    float acc[4][4][4];
    #pragma unroll
    for (int i = 0; i < 4; i++)
        #pragma unroll
        for (int j = 0; j < 4; j++)
            #pragma unroll
            for (int r = 0; r < 4; r++) acc[i][j][r] = 0.f;

    const int S = (K + 31) / 32;
    float4 av[4], bv[4];

    // prologue: load stage 0
    #pragma unroll
    for (int i = 0; i < 4; i++) {
        int idx = t + 256*i;
        int row = idx >> 3;
        int gk  = (idx & 7) * 4;
        av[i] = ld4g(A + (size_t)(bm + row)*lda + gk, gk < K);
        int n = bn + row;
        bv[i] = ld4g(B + (size_t)n*ldb + gk, (n < N) && (gk < K));
    }

    for (int s = 0; s < S; s++) {
        // store staged regs (convert fp32 -> bf16 hi/lo)
        #pragma unroll
        for (int i = 0; i < 4; i++) {
            int idx = t + 256*i;
            int row = idx >> 3;
            int k4  = (idx & 7) * 4;
            cvt_store(av[i], &Ahi[row*APAD + k4], &Alo[row*APAD + k4]);
            cvt_store(bv[i], &Bhi[row*APAD + k4], &Blo[row*APAD + k4]);
        }
        __syncthreads();

        // prefetch next stage while computing
        if (s + 1 < S) {
            int k0 = (s + 1) * 32;
            #pragma unroll
            for (int i = 0; i < 4; i++) {
                int idx = t + 256*i;
                int row = idx >> 3;
                int gk  = k0 + (idx & 7) * 4;
                av[i] = ld4g(A + (size_t)(bm + row)*lda + gk, gk < K);
                int n = bn + row;
                bv[i] = ld4g(B + (size_t)n*ldb + gk, (n < N) && (gk < K));
            }
        }

        // compute: 2 x k16 steps
        #pragma unroll
        for (int kk = 0; kk < 32; kk += 16) {
            uint32_t bh[4][2], bl[4][2];
            #pragma unroll
            for (int j = 0; j < 4; j++) {
                const __nv_bfloat16* bp = &Bhi[(wn + j*8 + g)*APAD + kk + q];
                bh[j][0] = *reinterpret_cast<const uint32_t*>(bp);
                bh[j][1] = *reinterpret_cast<const uint32_t*>(bp + 8);
                const __nv_bfloat16* bq = &Blo[(wn + j*8 + g)*APAD + kk + q];
                bl[j][0] = *reinterpret_cast<const uint32_t*>(bq);
                bl[j][1] = *reinterpret_cast<const uint32_t*>(bq + 8);
            }
            #pragma unroll
            for (int i = 0; i < 4; i++) {
                const __nv_bfloat16* ap = &Ahi[(wm + i*16 + g)*APAD + kk + q];
                uint32_t ah0 = *reinterpret_cast<const uint32_t*>(ap);
                uint32_t ah1 = *reinterpret_cast<const uint32_t*>(ap + 8*APAD);
                uint32_t ah2 = *reinterpret_cast<const uint32_t*>(ap + 8);
                uint32_t ah3 = *reinterpret_cast<const uint32_t*>(ap + 8*APAD + 8);
                const __nv_bfloat16* aq = &Alo[(wm + i*16 + g)*APAD + kk + q];
                uint32_t al0 = *reinterpret_cast<const uint32_t*>(aq);
                uint32_t al1 = *reinterpret_cast<const uint32_t*>(aq + 8*APAD);
                uint32_t al2 = *reinterpret_cast<const uint32_t*>(aq + 8);
                uint32_t al3 = *reinterpret_cast<const uint32_t*>(aq + 8*APAD + 8);
                #pragma unroll
                for (int j = 0; j < 4; j++) {
                    MMA_BF16(acc[i][j], ah0, ah1, ah2, ah3, bh[j][0], bh[j][1]);
                    MMA_BF16(acc[i][j], ah0, ah1, ah2, ah3, bl[j][0], bl[j][1]);
                    MMA_BF16(acc[i][j], al0, al1, al2, al3, bh[j][0], bh[j][1]);
                }
            }
        }
        __syncthreads();
    }

    // epilogue
    #pragma unroll
    for (int i = 0; i < 4; i++) {
        int r0 = bm + wm + i*16 + g;
        #pragma unroll
        for (int j = 0; j < 4; j++) {
            if (bn + wn + j*8 < N) {   // N is a multiple of 8
                int c = bn + wn + j*8 + q;
                float v0 = acc[i][j][0], v1 = acc[i][j][1];
                float v2 = acc[i][j][2], v3 = acc[i][j][3];
                if (EPI == 1) {
                    float b0 = bias[c], b1 = bias[c+1];
                    v0 = softplus_f(v0 + b0); v1 = softplus_f(v1 + b1);
                    v2 = softplus_f(v2 + b0); v3 = softplus_f(v3 + b1);
                }
                *reinterpret_cast<float2*>(&C[(size_t)r0*ldc + c])     = make_float2(v0, v1);
                *reinterpret_cast<float2*>(&C[(size_t)(r0+8)*ldc + c]) = make_float2(v2, v3);
            }
        }
    }
}

// ---------------- depthwise causal conv (width 4) + SiLU ----------------
__global__ void conv_silu_kernel(const float* __restrict__ xr,
                                 const float* __restrict__ w,
                                 const float* __restrict__ cb,
                                 float* __restrict__ out) {
    int idx = blockIdx.x * blockDim.x + threadIdx.x; // over NROWS*DINNER
    int d = idx % DINNER;
    int row = idx / DINNER;
    int l = row % LSEQ;
    const float* xp = xr + (size_t)row * (2*DINNER) + d;
    float acc = cb[d];
    const float* wp = w + d*4;
    #pragma unroll
    for (int j = 0; j < 4; j++) {
        int ll = l - 3 + j;
        if (ll >= 0) acc = fmaf(wp[j], xp[(long)(ll - l) * (2*DINNER)], acc);
    }
    out[idx] = acc / (1.f + __expf(-acc));
}

// ---------------- selective scan (+ D skip + gate) ----------------
// one thread per (b,d); 16 states in registers
__global__ void scan_kernel(const float* __restrict__ xc,
                            const float* __restrict__ delta,
                            const float* __restrict__ dbc,
                            const float* __restrict__ xr,
                            const float* __restrict__ A_log,
                            const float* __restrict__ Dp,
                            float* __restrict__ y) {
    int bidx = blockIdx.x;              // 24 blocks: 12 per batch
    int b = bidx / (DINNER/128);
    int d = (bidx % (DINNER/128)) * 128 + threadIdx.x;

    float a[16], h[16];
    #pragma unroll
    for (int n = 0; n < 16; n++) { a[n] = -expf(A_log[d*16 + n]); h[n] = 0.f; }
    float Dv = Dp[d];

    const float* dptr  = delta + (size_t)b*LSEQ*DINNER + d;
    const float* uptr  = xc    + (size_t)b*LSEQ*DINNER + d;
    const float* rptr  = xr    + (size_t)b*LSEQ*(2*DINNER) + DINNER + d;
    const float* bcptr = dbc   + (size_t)b*LSEQ*DBC_W + DTRANK;
    float* yptr        = y     + (size_t)b*LSEQ*DINNER + d;

    for (int l = 0; l < LSEQ; l++) {
        float dl = dptr[0];
        float u  = uptr[0];
        const float4* p = reinterpret_cast<const float4*>(bcptr);
        float4 t0=p[0], t1=p[1], t2=p[2], t3=p[3];   // B
        float4 c0=p[4], c1=p[5], c2=p[6], c3=p[7];   // C
        float bb[16] = {t0.x,t0.y,t0.z,t0.w, t1.x,t1.y,t1.z,t1.w,
                        t2.x,t2.y,t2.z,t2.w, t3.x,t3.y,t3.z,t3.w};
        float cc[16] = {c0.x,c0.y,c0.z,c0.w, c1.x,c1.y,c1.z,c1.w,
                        c2.x,c2.y,c2.z,c2.w, c3.x,c3.y,c3.z,c3.w};
        float du = dl * u;
        float accv = 0.f;
        #pragma unroll
        for (int n = 0; n < 16; n++) {
            float e = __expf(dl * a[n]);
            h[n] = fmaf(e, h[n], du * bb[n]);
            accv = fmaf(h[n], cc[n], accv);
        }
        float r = rptr[0];
        float gg = r / (1.f + __expf(-r));
        yptr[0] = (accv + u * Dv) * gg;

        dptr += DINNER; uptr += DINNER; rptr += 2*DINNER; bcptr += DBC_W; yptr += DINNER;
    }
}

// ---------------- launch ----------------
extern "C" void kernel_launch(void* const* d_in, const int* in_sizes, int n_in,
                              void* d_out, int out_size) {
    const float* x         = (const float*)d_in[0];
    const float* ln_w      = (const float*)d_in[1];
    const float* ln_b      = (const float*)d_in[2];
    const float* in_proj_w = (const float*)d_in[3];
    const float* conv_w    = (const float*)d_in[4];
    const float* conv_b    = (const float*)d_in[5];
    const float* x_proj_w  = (const float*)d_in[6];
    const float* dt_proj_w = (const float*)d_in[7];
    const float* dt_proj_b = (const float*)d_in[8];
    const float* A_log     = (const float*)d_in[9];
    const float* D_param   = (const float*)d_in[10];
    const float* out_proj_w= (const float*)d_in[11];
    float* out = (float*)d_out;

    float *p_xn, *p_xr, *p_xc, *p_dbc, *p_delta, *p_y;
    cudaGetSymbolAddress((void**)&p_xn, g_xn);
    cudaGetSymbolAddress((void**)&p_xr, g_xr);
    cudaGetSymbolAddress((void**)&p_xc, g_xc);
    cudaGetSymbolAddress((void**)&p_dbc, g_dbc);
    cudaGetSymbolAddress((void**)&p_delta, g_delta);
    cudaGetSymbolAddress((void**)&p_y, g_y);

    // 1. LayerNorm
    ln_kernel<<<NROWS, 256>>>(x, ln_w, ln_b, p_xn);

    // 2. in_proj: (4096x768) @ (3072x768)^T -> (4096x3072)
    mma_nt<0><<<dim3(2*DINNER/128, NROWS/128), 256>>>(
        p_xn, DMODEL, in_proj_w, DMODEL, p_xr, 2*DINNER, 2*DINNER, DMODEL, nullptr);

    // 3. conv + silu -> u
    conv_silu_kernel<<<(NROWS*DINNER)/256, 256>>>(p_xr, conv_w, conv_b, p_xc);

    // 4. x_proj: (4096x1536) @ (80x1536)^T -> (4096x80)
    mma_nt<0><<<dim3(1, NROWS/128), 256>>>(
        p_xc, DINNER, x_proj_w, DINNER, p_dbc, DBC_W, DBC_W, DINNER, nullptr);

    // 5. dt_proj + bias + softplus: (4096x48) @ (1536x48)^T -> (4096x1536)
    mma_nt<1><<<dim3(DINNER/128, NROWS/128), 256>>>(
        p_dbc, DBC_W, dt_proj_w, DTRANK, p_delta, DINNER, DINNER, DTRANK, dt_proj_b);

    // 6. selective scan + D skip + gate
    scan_kernel<<<BATCH*(DINNER/128), 128>>>(
        p_xc, p_delta, p_dbc, p_xr, A_log, D_param, p_y);

    // 7. out_proj: (4096x1536) @ (768x1536)^T -> (4096x768)
    mma_nt<0><<<dim3(DMODEL/128, NROWS/128), 256>>>(
        p_y, DINNER, out_proj_w, DINNER, out, DMODEL, DMODEL, DINNER, nullptr);
}

// round 6
// speedup vs baseline: 4.9199x; 3.7214x over previous
#include <cuda_runtime.h>
#include <cuda_bf16.h>
#include <stdint.h>
#include <math.h>

#define BATCH 2
#define LSEQ 2048
#define DMODEL 768
#define DINNER 1536
#define NSTATE 16
#define DTRANK 48
#define NROWS (BATCH*LSEQ)   /* 4096 */
#define DBC_W (DTRANK + 2*NSTATE)  /* 80 */

#define CHUNK 64
#define NCHUNK (LSEQ/CHUNK)  /* 32 */

#define APAD 40   /* bf16 elems per smem row (80B = 20-bank rotation, conflict-free) */

// ---- scratch (static device globals; no runtime allocation) ----
__device__ float g_xn[NROWS*DMODEL];           // layernorm out
__device__ float g_xr[(size_t)NROWS*2*DINNER]; // in_proj out (xin | res)
__device__ float g_xc[NROWS*DINNER];           // conv+silu out (u)
__device__ float g_dbc[NROWS*DBC_W];           // x_proj out (dt | B | C)
__device__ float g_delta[NROWS*DINNER];        // softplus(dt@W^T+b)
__device__ float g_y[NROWS*DINNER];            // scan out (pre-gate, then gated in place)
__device__ float g_hloc[(size_t)BATCH*NCHUNK*DINNER*NSTATE]; // per-chunk local terminal h
__device__ float g_hin [(size_t)BATCH*NCHUNK*DINNER*NSTATE]; // per-chunk input h
__device__ float g_dsum[BATCH*NCHUNK*DINNER];                // per-chunk sum(delta)

// ---------------- LayerNorm ----------------
__global__ void ln_kernel(const float* __restrict__ x,
                          const float* __restrict__ w,
                          const float* __restrict__ b,
                          float* __restrict__ out) {
    __shared__ float red[256];
    int row = blockIdx.x;
    int t = threadIdx.x;
    const float* xp = x + (size_t)row * DMODEL;
    float s = 0.f;
    #pragma unroll
    for (int i = 0; i < 3; i++) s += xp[t + i*256];
    red[t] = s; __syncthreads();
    for (int o = 128; o > 0; o >>= 1) { if (t < o) red[t] += red[t+o]; __syncthreads(); }
    float mu = red[0] / DMODEL;
    __syncthreads();
    float v = 0.f;
    #pragma unroll
    for (int i = 0; i < 3; i++) { float d = xp[t + i*256] - mu; v += d*d; }
    red[t] = v; __syncthreads();
    for (int o = 128; o > 0; o >>= 1) { if (t < o) red[t] += red[t+o]; __syncthreads(); }
    float rstd = rsqrtf(red[0] / DMODEL + 1e-5f);
    float* op = out + (size_t)row * DMODEL;
    #pragma unroll
    for (int i = 0; i < 3; i++) {
        int c = t + i*256;
        op[c] = (xp[c] - mu) * rstd * w[c] + b[c];
    }
}

__device__ __forceinline__ float softplus_f(float x) {
    return fmaxf(x, 0.f) + log1pf(expf(-fabsf(x)));
}

// ---------------- bf16-split tensor-core GEMM: C = A * B^T ----------------
#define MMA_BF16(C, A0,A1,A2,A3, B0,B1)                                   \
    asm volatile("mma.sync.aligned.m16n8k16.row.col.f32.bf16.bf16.f32 "   \
        "{%0,%1,%2,%3}, {%4,%5,%6,%7}, {%8,%9}, {%0,%1,%2,%3};"           \
        : "+f"(C[0]), "+f"(C[1]), "+f"(C[2]), "+f"(C[3])                  \
        : "r"(A0), "r"(A1), "r"(A2), "r"(A3), "r"(B0), "r"(B1))

__device__ __forceinline__ float4 ld4g(const float* p, bool pred) {
    if (pred) return *reinterpret_cast<const float4*>(p);
    return make_float4(0.f, 0.f, 0.f, 0.f);
}

__device__ __forceinline__ void cvt_store(float4 v,
                                          __nv_bfloat16* hi,
                                          __nv_bfloat16* lo) {
    __nv_bfloat16 h0 = __float2bfloat16(v.x), h1 = __float2bfloat16(v.y);
    __nv_bfloat16 h2 = __float2bfloat16(v.z), h3 = __float2bfloat16(v.w);
    __nv_bfloat16 l0 = __float2bfloat16(v.x - __bfloat162float(h0));
    __nv_bfloat16 l1 = __float2bfloat16(v.y - __bfloat162float(h1));
    __nv_bfloat16 l2 = __float2bfloat16(v.z - __bfloat162float(h2));
    __nv_bfloat16 l3 = __float2bfloat16(v.w - __bfloat162float(h3));
    __nv_bfloat162 p;
    p.x = h0; p.y = h1; *reinterpret_cast<__nv_bfloat162*>(hi)     = p;
    p.x = h2; p.y = h3; *reinterpret_cast<__nv_bfloat162*>(hi + 2) = p;
    p.x = l0; p.y = l1; *reinterpret_cast<__nv_bfloat162*>(lo)     = p;
    p.x = l2; p.y = l3; *reinterpret_cast<__nv_bfloat162*>(lo + 2) = p;
}

template<int EPI>
__global__ __launch_bounds__(256, 1)
void mma_nt(const float* __restrict__ A, int lda,
            const float* __restrict__ B, int ldb,
            float* __restrict__ C, int ldc,
            int N, int K,
            const float* __restrict__ bias) {
    __shared__ __nv_bfloat16 Ahi[128*APAD];
    __shared__ __nv_bfloat16 Alo[128*APAD];
    __shared__ __nv_bfloat16 Bhi[128*APAD];
    __shared__ __nv_bfloat16 Blo[128*APAD];

    const int t = threadIdx.x;
    const int bm = blockIdx.y * 128;
    const int bn = blockIdx.x * 128;
    const int warp = t >> 5, lane = t & 31;
    const int wm = (warp >> 2) * 64;
    const int wn = (warp & 3) * 32;
    const int g = lane >> 2;
    const int q = (lane & 3) * 2;

    float acc[4][4][4];
    #pragma unroll
    for (int i = 0; i < 4; i++)
        #pragma unroll
        for (int j = 0; j < 4; j++)
            #pragma unroll
            for (int r = 0; r < 4; r++) acc[i][j][r] = 0.f;

    const int S = (K + 31) / 32;
    float4 av[4], bv[4];

    #pragma unroll
    for (int i = 0; i < 4; i++) {
        int idx = t + 256*i;
        int row = idx >> 3;
        int gk  = (idx & 7) * 4;
        av[i] = ld4g(A + (size_t)(bm + row)*lda + gk, gk < K);
        int n = bn + row;
        bv[i] = ld4g(B + (size_t)n*ldb + gk, (n < N) && (gk < K));
    }

    for (int s = 0; s < S; s++) {
        #pragma unroll
        for (int i = 0; i < 4; i++) {
            int idx = t + 256*i;
            int row = idx >> 3;
            int k4  = (idx & 7) * 4;
            cvt_store(av[i], &Ahi[row*APAD + k4], &Alo[row*APAD + k4]);
            cvt_store(bv[i], &Bhi[row*APAD + k4], &Blo[row*APAD + k4]);
        }
        __syncthreads();

        if (s + 1 < S) {
            int k0 = (s + 1) * 32;
            #pragma unroll
            for (int i = 0; i < 4; i++) {
                int idx = t + 256*i;
                int row = idx >> 3;
                int gk  = k0 + (idx & 7) * 4;
                av[i] = ld4g(A + (size_t)(bm + row)*lda + gk, gk < K);
                int n = bn + row;
                bv[i] = ld4g(B + (size_t)n*ldb + gk, (n < N) && (gk < K));
            }
        }

        #pragma unroll
        for (int kk = 0; kk < 32; kk += 16) {
            uint32_t bh[4][2], bl[4][2];
            #pragma unroll
            for (int j = 0; j < 4; j++) {
                const __nv_bfloat16* bp = &Bhi[(wn + j*8 + g)*APAD + kk + q];
                bh[j][0] = *reinterpret_cast<const uint32_t*>(bp);
                bh[j][1] = *reinterpret_cast<const uint32_t*>(bp + 8);
                const __nv_bfloat16* bq = &Blo[(wn + j*8 + g)*APAD + kk + q];
                bl[j][0] = *reinterpret_cast<const uint32_t*>(bq);
                bl[j][1] = *reinterpret_cast<const uint32_t*>(bq + 8);
            }
            #pragma unroll
            for (int i = 0; i < 4; i++) {
                const __nv_bfloat16* ap = &Ahi[(wm + i*16 + g)*APAD + kk + q];
                uint32_t ah0 = *reinterpret_cast<const uint32_t*>(ap);
                uint32_t ah1 = *reinterpret_cast<const uint32_t*>(ap + 8*APAD);
                uint32_t ah2 = *reinterpret_cast<const uint32_t*>(ap + 8);
                uint32_t ah3 = *reinterpret_cast<const uint32_t*>(ap + 8*APAD + 8);
                const __nv_bfloat16* aq = &Alo[(wm + i*16 + g)*APAD + kk + q];
                uint32_t al0 = *reinterpret_cast<const uint32_t*>(aq);
                uint32_t al1 = *reinterpret_cast<const uint32_t*>(aq + 8*APAD);
                uint32_t al2 = *reinterpret_cast<const uint32_t*>(aq + 8);
                uint32_t al3 = *reinterpret_cast<const uint32_t*>(aq + 8*APAD + 8);
                #pragma unroll
                for (int j = 0; j < 4; j++) {
                    MMA_BF16(acc[i][j], ah0, ah1, ah2, ah3, bh[j][0], bh[j][1]);
                    MMA_BF16(acc[i][j], ah0, ah1, ah2, ah3, bl[j][0], bl[j][1]);
                    MMA_BF16(acc[i][j], al0, al1, al2, al3, bh[j][0], bh[j][1]);
                }
            }
        }
        __syncthreads();
    }

    #pragma unroll
    for (int i = 0; i < 4; i++) {
        int r0 = bm + wm + i*16 + g;
        #pragma unroll
        for (int j = 0; j < 4; j++) {
            if (bn + wn + j*8 < N) {
                int c = bn + wn + j*8 + q;
                float v0 = acc[i][j][0], v1 = acc[i][j][1];
                float v2 = acc[i][j][2], v3 = acc[i][j][3];
                if (EPI == 1) {
                    float b0 = bias[c], b1 = bias[c+1];
                    v0 = softplus_f(v0 + b0); v1 = softplus_f(v1 + b1);
                    v2 = softplus_f(v2 + b0); v3 = softplus_f(v3 + b1);
                }
                *reinterpret_cast<float2*>(&C[(size_t)r0*ldc + c])     = make_float2(v0, v1);
                *reinterpret_cast<float2*>(&C[(size_t)(r0+8)*ldc + c]) = make_float2(v2, v3);
            }
        }
    }
}

// ---------------- depthwise causal conv (width 4) + SiLU ----------------
__global__ void conv_silu_kernel(const float* __restrict__ xr,
                                 const float* __restrict__ w,
                                 const float* __restrict__ cb,
                                 float* __restrict__ out) {
    int idx = blockIdx.x * blockDim.x + threadIdx.x;
    int d = idx % DINNER;
    int row = idx / DINNER;
    int l = row % LSEQ;
    const float* xp = xr + (size_t)row * (2*DINNER) + d;
    float acc = cb[d];
    const float* wp = w + d*4;
    #pragma unroll
    for (int j = 0; j < 4; j++) {
        int ll = l - 3 + j;
        if (ll >= 0) acc = fmaf(wp[j], xp[(long)(ll - l) * (2*DINNER)], acc);
    }
    out[idx] = acc / (1.f + __expf(-acc));
}

// ---------------- selective scan: pass 1 (local chunk scan) ----------------
// grid (DINNER/128, NCHUNK, BATCH), block 128.
// Scans its 64-step chunk from h=0, writes pre-gate partial y, terminal h, sum(delta).
__global__ void scan_chunk_kernel(const float* __restrict__ xc,
                                  const float* __restrict__ delta,
                                  const float* __restrict__ dbc,
                                  const float* __restrict__ A_log,
                                  const float* __restrict__ Dp,
                                  float* __restrict__ ypre,
                                  float* __restrict__ hloc,
                                  float* __restrict__ dsum) {
    int d = blockIdx.x * 128 + threadIdx.x;
    int c = blockIdx.y;
    int b = blockIdx.z;
    int l0 = c * CHUNK;

    float a[16], h[16];
    #pragma unroll
    for (int n = 0; n < 16; n++) { a[n] = -expf(A_log[d*16 + n]); h[n] = 0.f; }
    float Dv = Dp[d];

    const float* dptr  = delta + ((size_t)b*LSEQ + l0)*DINNER + d;
    const float* uptr  = xc    + ((size_t)b*LSEQ + l0)*DINNER + d;
    const float* bcptr = dbc   + ((size_t)b*LSEQ + l0)*DBC_W + DTRANK;
    float* yptr        = ypre  + ((size_t)b*LSEQ + l0)*DINNER + d;

    float S = 0.f;
    #pragma unroll 2
    for (int l = 0; l < CHUNK; l++) {
        float dl = dptr[0];
        float u  = uptr[0];
        const float4* p = reinterpret_cast<const float4*>(bcptr);
        float4 t0=p[0], t1=p[1], t2=p[2], t3=p[3];
        float4 c0=p[4], c1=p[5], c2=p[6], c3=p[7];
        float bb[16] = {t0.x,t0.y,t0.z,t0.w, t1.x,t1.y,t1.z,t1.w,
                        t2.x,t2.y,t2.z,t2.w, t3.x,t3.y,t3.z,t3.w};
        float cc[16] = {c0.x,c0.y,c0.z,c0.w, c1.x,c1.y,c1.z,c1.w,
                        c2.x,c2.y,c2.z,c2.w, c3.x,c3.y,c3.z,c3.w};
        S += dl;
        float du = dl * u;
        float accv = 0.f;
        #pragma unroll
        for (int n = 0; n < 16; n++) {
            float e = __expf(dl * a[n]);
            h[n] = fmaf(e, h[n], du * bb[n]);
            accv = fmaf(h[n], cc[n], accv);
        }
        yptr[0] = accv + u * Dv;   // pre-gate partial (missing h_in contribution)
        dptr += DINNER; uptr += DINNER; bcptr += DBC_W; yptr += DINNER;
    }

    size_t hb = ((size_t)(b*NCHUNK + c)*DINNER + d) * 16;
    #pragma unroll
    for (int n = 0; n < 16; n++) hloc[hb + n] = h[n];
    dsum[(b*NCHUNK + c)*DINNER + d] = S;
}

// ---------------- selective scan: combine (sequential over chunks) ----------------
// one thread per (b,d,n): h_in[c] = exp(a*dsum[c-1])*h_in[c-1] + hloc[c-1]
__global__ void scan_combine_kernel(const float* __restrict__ hloc,
                                    const float* __restrict__ dsum,
                                    const float* __restrict__ A_log,
                                    float* __restrict__ hin) {
    int idx = blockIdx.x * blockDim.x + threadIdx.x;  // BATCH*DINNER*16
    int n = idx & 15;
    int d = (idx >> 4) % DINNER;
    int b = idx / (DINNER*16);
    float a = -expf(A_log[d*16 + n]);
    float h = 0.f;
    for (int c = 0; c < NCHUNK; c++) {
        size_t base = ((size_t)(b*NCHUNK + c)*DINNER + d);
        hin[base*16 + n] = h;
        float P = __expf(a * dsum[base]);
        h = fmaf(P, h, hloc[base*16 + n]);
    }
}

// ---------------- selective scan: pass 2 (correction + gate) ----------------
// y = (ypre + sum_n C_t[n]*exp(a[n]*cumdelta_t)*h_in[n]) * silu(res)
__global__ void scan_fix_kernel(const float* __restrict__ delta,
                                const float* __restrict__ dbc,
                                const float* __restrict__ xr,
                                const float* __restrict__ A_log,
                                const float* __restrict__ hin,
                                float* __restrict__ y) {
    int d = blockIdx.x * 128 + threadIdx.x;
    int c = blockIdx.y;
    int b = blockIdx.z;
    int l0 = c * CHUNK;

    const float* dptr  = delta + ((size_t)b*LSEQ + l0)*DINNER + d;
    const float* rptr  = xr    + ((size_t)b*LSEQ + l0)*(2*DINNER) + DINNER + d;
    const float* bcptr = dbc   + ((size_t)b*LSEQ + l0)*DBC_W + DTRANK + NSTATE; // C part
    float* yptr        = y     + ((size_t)b*LSEQ + l0)*DINNER + d;

    if (c == 0) {
        // no correction; just gate
        #pragma unroll 4
        for (int l = 0; l < CHUNK; l++) {
            float r = rptr[0];
            float gg = r / (1.f + __expf(-r));
            yptr[0] = yptr[0] * gg;
            rptr += 2*DINNER; yptr += DINNER;
        }
        return;
    }

    float a[16], hv[16];
    size_t hb = ((size_t)(b*NCHUNK + c)*DINNER + d) * 16;
    #pragma unroll
    for (int n = 0; n < 16; n++) {
        a[n] = -expf(A_log[d*16 + n]);
        hv[n] = hin[hb + n];
    }

    float S = 0.f;
    #pragma unroll 2
    for (int l = 0; l < CHUNK; l++) {
        float dl = dptr[0];
        S += dl;
        const float4* p = reinterpret_cast<const float4*>(bcptr);
        float4 c0=p[0], c1=p[1], c2=p[2], c3=p[3];
        float cc[16] = {c0.x,c0.y,c0.z,c0.w, c1.x,c1.y,c1.z,c1.w,
                        c2.x,c2.y,c2.z,c2.w, c3.x,c3.y,c3.z,c3.w};
        float corr = 0.f;
        #pragma unroll
        for (int n = 0; n < 16; n++) {
            corr = fmaf(cc[n] * hv[n], __expf(a[n] * S), corr);
        }
        float r = rptr[0];
        float gg = r / (1.f + __expf(-r));
        yptr[0] = (yptr[0] + corr) * gg;
        dptr += DINNER; rptr += 2*DINNER; bcptr += DBC_W; yptr += DINNER;
    }
}

// ---------------- launch ----------------
extern "C" void kernel_launch(void* const* d_in, const int* in_sizes, int n_in,
                              void* d_out, int out_size) {
    const float* x         = (const float*)d_in[0];
    const float* ln_w      = (const float*)d_in[1];
    const float* ln_b      = (const float*)d_in[2];
    const float* in_proj_w = (const float*)d_in[3];
    const float* conv_w    = (const float*)d_in[4];
    const float* conv_b    = (const float*)d_in[5];
    const float* x_proj_w  = (const float*)d_in[6];
    const float* dt_proj_w = (const float*)d_in[7];
    const float* dt_proj_b = (const float*)d_in[8];
    const float* A_log     = (const float*)d_in[9];
    const float* D_param   = (const float*)d_in[10];
    const float* out_proj_w= (const float*)d_in[11];
    float* out = (float*)d_out;

    float *p_xn, *p_xr, *p_xc, *p_dbc, *p_delta, *p_y, *p_hloc, *p_hin, *p_dsum;
    cudaGetSymbolAddress((void**)&p_xn, g_xn);
    cudaGetSymbolAddress((void**)&p_xr, g_xr);
    cudaGetSymbolAddress((void**)&p_xc, g_xc);
    cudaGetSymbolAddress((void**)&p_dbc, g_dbc);
    cudaGetSymbolAddress((void**)&p_delta, g_delta);
    cudaGetSymbolAddress((void**)&p_y, g_y);
    cudaGetSymbolAddress((void**)&p_hloc, g_hloc);
    cudaGetSymbolAddress((void**)&p_hin, g_hin);
    cudaGetSymbolAddress((void**)&p_dsum, g_dsum);

    // 1. LayerNorm
    ln_kernel<<<NROWS, 256>>>(x, ln_w, ln_b, p_xn);

    // 2. in_proj
    mma_nt<0><<<dim3(2*DINNER/128, NROWS/128), 256>>>(
        p_xn, DMODEL, in_proj_w, DMODEL, p_xr, 2*DINNER, 2*DINNER, DMODEL, nullptr);

    // 3. conv + silu -> u
    conv_silu_kernel<<<(NROWS*DINNER)/256, 256>>>(p_xr, conv_w, conv_b, p_xc);

    // 4. x_proj
    mma_nt<0><<<dim3(1, NROWS/128), 256>>>(
        p_xc, DINNER, x_proj_w, DINNER, p_dbc, DBC_W, DBC_W, DINNER, nullptr);

    // 5. dt_proj + bias + softplus
    mma_nt<1><<<dim3(DINNER/128, NROWS/128), 256>>>(
        p_dbc, DBC_W, dt_proj_w, DTRANK, p_delta, DINNER, DINNER, DTRANK, dt_proj_b);

    // 6. selective scan: chunked two-pass
    dim3 sgrid(DINNER/128, NCHUNK, BATCH);
    scan_chunk_kernel<<<sgrid, 128>>>(p_xc, p_delta, p_dbc, A_log, D_param,
                                      p_y, p_hloc, p_dsum);
    scan_combine_kernel<<<(BATCH*DINNER*16)/256, 256>>>(p_hloc, p_dsum, A_log, p_hin);
    scan_fix_kernel<<<sgrid, 128>>>(p_delta, p_dbc, p_xr, A_log, p_hin, p_y);

    // 7. out_proj
    mma_nt<0><<<dim3(DMODEL/128, NROWS/128), 256>>>(
        p_y, DINNER, out_proj_w, DINNER, out, DMODEL, DMODEL, DINNER, nullptr);
}